// round 14
// baseline (speedup 1.0000x reference)
#include <cuda_runtime.h>

#define TPB 128
#define NP  64    // problems per block (2 threads per problem)
#define XPAD 62   // per-problem smem stride (even -> 8B-aligned LDS.64)

typedef unsigned long long ull;

__device__ __forceinline__ ull pk(float lo, float hi) {
    ull r; asm("mov.b64 %0, {%1, %2};" : "=l"(r) : "f"(lo), "f"(hi)); return r;
}
__device__ __forceinline__ float lo2(ull v) { return __uint_as_float((unsigned)v); }
__device__ __forceinline__ float hi2(ull v) { return __uint_as_float((unsigned)(v >> 32)); }
__device__ __forceinline__ ull fma2(ull a, ull b, ull c) {
    ull d; asm("fma.rn.f32x2 %0, %1, %2, %3;" : "=l"(d) : "l"(a), "l"(b), "l"(c)); return d;
}
__device__ __forceinline__ ull mul2(ull a, ull b) {
    ull d; asm("mul.rn.f32x2 %0, %1, %2;" : "=l"(d) : "l"(a), "l"(b)); return d;
}
__device__ __forceinline__ ull add2(ull a, ull b) {
    ull d; asm("add.rn.f32x2 %0, %1, %2;" : "=l"(d) : "l"(a), "l"(b)); return d;
}
__device__ __forceinline__ float ex2(float x) {
    float r; asm("ex2.approx.f32 %0, %1;" : "=f"(r) : "f"(x)); return r;
}

// TWO threads per problem (lane pair t, t^1). Role A (t&1==0): key-pair slots {0,1,2};
// role B: slots {3,4,4} with the duplicate slot's exp weighted by 0 (uniform code, no
// divergence). Partial softmax num/den combined via shfl_xor(1). Transposed smem layout
// x[j][d] at d*10+j; packed-over-keys fma2 math as before.
// S'_ij = (x_i^T M x_j + r.x_j)*log2(e); out_i = sum 2^s vsum / sum 2^s.
__global__ __launch_bounds__(TPB, 4) void attn_kernel(
    const float* __restrict__ x,
    const float* __restrict__ Wk, const float* __restrict__ bk,
    const float* __restrict__ Wq, const float* __restrict__ bq,
    const float* __restrict__ Wv, const float* __restrict__ bv,
    float* __restrict__ out)
{
    __shared__ float2 cst[49];
    __shared__ float  xs[NP * XPAD];
    const int t = threadIdx.x;

    // ---- per-block precompute of dup-packed constants ----
    if (t < 49) {
        const float L2E = 1.4426950408889634f;
        float s = 0.f;
        if (t < 36) {                    // M[a][b] = sum_e Wq[e][a] Wk[e][b]  (*L2E)
            int a = t / 6, b = t % 6;
            #pragma unroll
            for (int e = 0; e < 6; e++) s += Wq[e*6 + a] * Wk[e*6 + b];
            s *= L2E;
        } else if (t < 42) {             // r[b] = sum_e bq[e] Wk[e][b]  (*L2E)
            int b = t - 36;
            #pragma unroll
            for (int e = 0; e < 6; e++) s += bq[e] * Wk[e*6 + b];
            s *= L2E;
        } else if (t < 48) {             // wv[d] = colsum(Wv)
            int d = t - 42;
            #pragma unroll
            for (int e = 0; e < 6; e++) s += Wv[e*6 + d];
        } else {                         // cv = sum(bv)
            #pragma unroll
            for (int e = 0; e < 6; e++) s += bv[e];
        }
        cst[t] = make_float2(s, s);
    }

    // ---- staging (threads 0..119): 8 float4 each; 480-float stride = exactly 8 problems ----
    if (t < 120) {
        const float4* xg = (const float4*)(x + (size_t)blockIdx.x * (NP * 60)) + t;
        int tb = (4 * t) / 60;
        int te = 4 * t - 60 * tb;
        int j0 = te / 6, d0 = te - 6 * j0;
        int ro = (d0 == 4) ? 59 : 0;
        int a0 = tb * XPAD + d0 * 10 + j0;
        #pragma unroll
        for (int i = 0; i < 8; i++) {
            float4 v = xg[i * 120];
            xs[a0]           = v.x;
            xs[a0 + 10]      = v.y;
            xs[a0 + 20 - ro] = v.z;
            xs[a0 + 30 - ro] = v.w;
            a0 += 8 * XPAD;
        }
    }
    __syncthreads();

    const int p    = t >> 1;             // problem within block
    const int role = t & 1;              // 0: keys 0-5, 1: keys 6-9
    const float* xp = &xs[p * XPAD];
    const ull*   XX = (const ull*)xp;    // XX[d*5 + m] = (x[2m][d], x[2m+1][d])
    const ull*   C  = reinterpret_cast<const ull*>(cst);

    const int k0 = role ? 3 : 0;
    const int k1 = role ? 4 : 1;
    const int k2 = role ? 4 : 2;         // duplicate slot for role B, weighted 0
    const float wt = role ? 0.f : 1.f;
    const ull  wt2 = pk(wt, wt);

    // ---- phase 1 (this role's 3 slots): G = M x pair, hp = r.x, vp = wv.x + cv ----
    ull G[6][3], hp[3], vp[3];
    {   // d = 0
        ull xx0 = XX[k0], xx1 = XX[k1], xx2 = XX[k2];
        #pragma unroll
        for (int a = 0; a < 6; a++) {
            ull m = C[a*6];
            G[a][0] = mul2(m, xx0); G[a][1] = mul2(m, xx1); G[a][2] = mul2(m, xx2);
        }
        ull r = C[36], w = C[42], cv = C[48];
        hp[0] = mul2(r, xx0); hp[1] = mul2(r, xx1); hp[2] = mul2(r, xx2);
        vp[0] = fma2(w, xx0, cv); vp[1] = fma2(w, xx1, cv); vp[2] = fma2(w, xx2, cv);
    }
    #pragma unroll
    for (int d = 1; d < 6; d++) {
        ull xx0 = XX[d*5 + k0], xx1 = XX[d*5 + k1], xx2 = XX[d*5 + k2];
        #pragma unroll
        for (int a = 0; a < 6; a++) {
            ull m = C[a*6 + d];
            G[a][0] = fma2(m, xx0, G[a][0]);
            G[a][1] = fma2(m, xx1, G[a][1]);
            G[a][2] = fma2(m, xx2, G[a][2]);
        }
        ull r = C[36 + d], w = C[42 + d];
        hp[0] = fma2(r, xx0, hp[0]); hp[1] = fma2(r, xx1, hp[1]); hp[2] = fma2(r, xx2, hp[2]);
        vp[0] = fma2(w, xx0, vp[0]); vp[1] = fma2(w, xx1, vp[1]); vp[2] = fma2(w, xx2, vp[2]);
    }

    // ---- phase 2: partial num/den over this role's keys, query pairs (2 chains) ----
    float num[10], den[10];
    #pragma unroll
    for (int ip = 0; ip < 5; ip++) {
        ull XA[6], XB[6];
        #pragma unroll
        for (int a = 0; a < 6; a++) {
            ull xq = XX[a*5 + ip];       // lane pair reads same addr -> smem broadcast
            float xa = lo2(xq), xb = hi2(xq);
            XA[a] = pk(xa, xa);
            XB[a] = pk(xb, xb);
        }
        ull nA, dA, nB, dB;
        {   // slot 0
            ull sA = fma2(XA[0], G[0][0], hp[0]);
            ull sB = fma2(XB[0], G[0][0], hp[0]);
            #pragma unroll
            for (int a = 1; a < 6; a++) {
                sA = fma2(XA[a], G[a][0], sA);
                sB = fma2(XB[a], G[a][0], sB);
            }
            ull eA = pk(ex2(lo2(sA)), ex2(hi2(sA)));
            ull eB = pk(ex2(lo2(sB)), ex2(hi2(sB)));
            nA = mul2(eA, vp[0]);  dA = eA;
            nB = mul2(eB, vp[0]);  dB = eB;
        }
        {   // slot 1
            ull sA = fma2(XA[0], G[0][1], hp[1]);
            ull sB = fma2(XB[0], G[0][1], hp[1]);
            #pragma unroll
            for (int a = 1; a < 6; a++) {
                sA = fma2(XA[a], G[a][1], sA);
                sB = fma2(XB[a], G[a][1], sB);
            }
            ull eA = pk(ex2(lo2(sA)), ex2(hi2(sA)));
            ull eB = pk(ex2(lo2(sB)), ex2(hi2(sB)));
            nA = fma2(eA, vp[1], nA);  dA = add2(dA, eA);
            nB = fma2(eB, vp[1], nB);  dB = add2(dB, eB);
        }
        {   // slot 2 (weighted: zero for role B's duplicate)
            ull sA = fma2(XA[0], G[0][2], hp[2]);
            ull sB = fma2(XB[0], G[0][2], hp[2]);
            #pragma unroll
            for (int a = 1; a < 6; a++) {
                sA = fma2(XA[a], G[a][2], sA);
                sB = fma2(XB[a], G[a][2], sB);
            }
            ull eA = mul2(pk(ex2(lo2(sA)), ex2(hi2(sA))), wt2);
            ull eB = mul2(pk(ex2(lo2(sB)), ex2(hi2(sB))), wt2);
            nA = fma2(eA, vp[2], nA);  dA = add2(dA, eA);
            nB = fma2(eB, vp[2], nB);  dB = add2(dB, eB);
        }
        num[2*ip]     = lo2(nA) + hi2(nA);  den[2*ip]     = lo2(dA) + hi2(dA);
        num[2*ip + 1] = lo2(nB) + hi2(nB);  den[2*ip + 1] = lo2(dB) + hi2(dB);
    }

    // ---- combine partner partials (uniform code: all lanes participate) ----
    #pragma unroll
    for (int i = 0; i < 10; i++) {
        num[i] += __shfl_xor_sync(0xFFFFFFFFu, num[i], 1);
        den[i] += __shfl_xor_sync(0xFFFFFFFFu, den[i], 1);
    }

    // ---- each thread divides + writes its 5 queries (contiguous per lane pair) ----
    const int qb = role * 5;
    float* op = out + (size_t)(blockIdx.x * NP + p) * 10 + qb;
    #pragma unroll
    for (int k = 0; k < 5; k++)
        op[k] = __fdividef(num[qb + k], den[qb + k]);
}

extern "C" void kernel_launch(void* const* d_in, const int* in_sizes, int n_in,
                              void* d_out, int out_size) {
    const float* x  = (const float*)d_in[0];
    const float* Wk = (const float*)d_in[1];
    const float* bk = (const float*)d_in[2];
    const float* Wq = (const float*)d_in[3];
    const float* bq = (const float*)d_in[4];
    const float* Wv = (const float*)d_in[5];
    const float* bv = (const float*)d_in[6];
    int B = in_sizes[0] / 60;            // 524288
    int blocks = B / NP;                 // 8192
    attn_kernel<<<blocks, TPB>>>(x, Wk, bk, Wq, bq, Wv, bv, (float*)d_out);
}

// round 15
// speedup vs baseline: 1.2395x; 1.2395x over previous
#include <cuda_runtime.h>

#define TPB 128
#define XPAD 62   // per-problem smem stride (even -> 8B-aligned LDS.64; 2-way conflicts max)

typedef unsigned long long ull;

__device__ __forceinline__ ull pk(float lo, float hi) {
    ull r; asm("mov.b64 %0, {%1, %2};" : "=l"(r) : "f"(lo), "f"(hi)); return r;
}
__device__ __forceinline__ float lo2(ull v) { return __uint_as_float((unsigned)v); }
__device__ __forceinline__ float hi2(ull v) { return __uint_as_float((unsigned)(v >> 32)); }
__device__ __forceinline__ ull fma2(ull a, ull b, ull c) {
    ull d; asm("fma.rn.f32x2 %0, %1, %2, %3;" : "=l"(d) : "l"(a), "l"(b), "l"(c)); return d;
}
__device__ __forceinline__ ull mul2(ull a, ull b) {
    ull d; asm("mul.rn.f32x2 %0, %1, %2;" : "=l"(d) : "l"(a), "l"(b)); return d;
}
__device__ __forceinline__ float ex2(float x) {
    float r; asm("ex2.approx.f32 %0, %1;" : "=f"(r) : "f"(x)); return r;
}

// One thread = one batch problem. Transposed smem: x[j][d] at d*10+j.
// Phase 2 restructured for ILP: per query pair, ALL 10 packed score chains are
// computed first (10 independent 6-deep fma2 chains), then 20 ex2 batched, then
// scalar num/den accumulation (the schedule shape that won in R10).
// S'_ij = (x_i^T M x_j + r.x_j)*log2(e); out_i = sum 2^s vsum / sum 2^s.
// smem constants (dup-packed float2): [0..35] M*L2E, [36..41] r*L2E, [42..47] wv, [48] cv
__global__ __launch_bounds__(TPB, 3) void attn_kernel(
    const float* __restrict__ x,
    const float* __restrict__ Wk, const float* __restrict__ bk,
    const float* __restrict__ Wq, const float* __restrict__ bq,
    const float* __restrict__ Wv, const float* __restrict__ bv,
    float* __restrict__ out)
{
    __shared__ float2 cst[49];
    __shared__ float  xs[TPB * XPAD];
    const int t = threadIdx.x;

    // ---- per-block precompute of dup-packed constants ----
    if (t < 49) {
        const float L2E = 1.4426950408889634f;
        float s = 0.f;
        if (t < 36) {                    // M[a][b] = sum_e Wq[e][a] Wk[e][b]  (*L2E)
            int a = t / 6, b = t % 6;
            #pragma unroll
            for (int e = 0; e < 6; e++) s += Wq[e*6 + a] * Wk[e*6 + b];
            s *= L2E;
        } else if (t < 42) {             // r[b] = sum_e bq[e] Wk[e][b]  (*L2E)
            int b = t - 36;
            #pragma unroll
            for (int e = 0; e < 6; e++) s += bq[e] * Wk[e*6 + b];
            s *= L2E;
        } else if (t < 48) {             // wv[d] = colsum(Wv)
            int d = t - 42;
            #pragma unroll
            for (int e = 0; e < 6; e++) s += Wv[e*6 + d];
        } else {                         // cv = sum(bv)
            #pragma unroll
            for (int e = 0; e < 6; e++) s += bv[e];
        }
        cst[t] = make_float2(s, s);
    }

    // ---- staging (threads 0..119): 16 float4 each, loop-invariant transpose addressing ----
    if (t < 120) {
        const float4* xg = (const float4*)(x + (size_t)blockIdx.x * (TPB * 60)) + t;
        int tb = (4 * t) / 60;
        int te = 4 * t - 60 * tb;
        int j0 = te / 6, d0 = te - 6 * j0;
        int ro = (d0 == 4) ? 59 : 0;
        int a0 = tb * XPAD + d0 * 10 + j0;
        #pragma unroll
        for (int i = 0; i < 16; i++) {
            float4 v = xg[i * 120];
            xs[a0]           = v.x;
            xs[a0 + 10]      = v.y;
            xs[a0 + 20 - ro] = v.z;
            xs[a0 + 30 - ro] = v.w;
            a0 += 8 * XPAD;
        }
    }
    __syncthreads();

    const float* xp = &xs[t * XPAD];
    const ull*   XX = (const ull*)xp;               // XX[d*5 + m] = (x[2m][d], x[2m+1][d])
    const ull*   C  = reinterpret_cast<const ull*>(cst);

    // ---- phase 1, d-outer, fully packed ----
    ull G[6][5], hp[5], vp[5];
    {   // d = 0
        ull xx0 = XX[0], xx1 = XX[1], xx2 = XX[2], xx3 = XX[3], xx4 = XX[4];
        #pragma unroll
        for (int a = 0; a < 6; a++) {
            ull m = C[a*6];
            G[a][0] = mul2(m, xx0); G[a][1] = mul2(m, xx1); G[a][2] = mul2(m, xx2);
            G[a][3] = mul2(m, xx3); G[a][4] = mul2(m, xx4);
        }
        ull r = C[36], w = C[42], cv = C[48];
        hp[0] = mul2(r, xx0); hp[1] = mul2(r, xx1); hp[2] = mul2(r, xx2);
        hp[3] = mul2(r, xx3); hp[4] = mul2(r, xx4);
        vp[0] = fma2(w, xx0, cv); vp[1] = fma2(w, xx1, cv); vp[2] = fma2(w, xx2, cv);
        vp[3] = fma2(w, xx3, cv); vp[4] = fma2(w, xx4, cv);
    }
    #pragma unroll
    for (int d = 1; d < 6; d++) {
        ull xx[5];
        #pragma unroll
        for (int jp = 0; jp < 5; jp++) xx[jp] = XX[d*5 + jp];
        #pragma unroll
        for (int a = 0; a < 6; a++) {
            ull m = C[a*6 + d];
            #pragma unroll
            for (int jp = 0; jp < 5; jp++) G[a][jp] = fma2(m, xx[jp], G[a][jp]);
        }
        ull r = C[36 + d], w = C[42 + d];
        #pragma unroll
        for (int jp = 0; jp < 5; jp++) {
            hp[jp] = fma2(r, xx[jp], hp[jp]);
            vp[jp] = fma2(w, xx[jp], vp[jp]);
        }
    }

    // ---- phase 2: query pairs; ALL scores -> ALL ex2 -> scalar accumulate ----
    float res[10];
    #pragma unroll
    for (int ip = 0; ip < 5; ip++) {     // queries 2ip, 2ip+1
        ull XA[6], XB[6];
        #pragma unroll
        for (int a = 0; a < 6; a++) {
            ull xq = XX[a*5 + ip];       // one LDS.64 serves both queries
            float xa = lo2(xq), xb = hi2(xq);
            XA[a] = pk(xa, xa);
            XB[a] = pk(xb, xb);
        }

        // 10 independent 6-deep fma2 chains (max ILP before any MUFU)
        ull sA[5], sB[5];
        #pragma unroll
        for (int jp = 0; jp < 5; jp++) {
            ull a0 = fma2(XA[0], G[0][jp], hp[jp]);
            ull b0 = fma2(XB[0], G[0][jp], hp[jp]);
            #pragma unroll
            for (int a = 1; a < 6; a++) {
                a0 = fma2(XA[a], G[a][jp], a0);
                b0 = fma2(XB[a], G[a][jp], b0);
            }
            sA[jp] = a0;
            sB[jp] = b0;
        }

        // 20 ex2 batched back-to-back
        float eA[10], eB[10];
        #pragma unroll
        for (int jp = 0; jp < 5; jp++) {
            eA[2*jp]     = ex2(lo2(sA[jp]));
            eA[2*jp + 1] = ex2(hi2(sA[jp]));
            eB[2*jp]     = ex2(lo2(sB[jp]));
            eB[2*jp + 1] = ex2(hi2(sB[jp]));
        }

        // scalar accumulate (R10's winning tail shape)
        float numA = 0.f, denA = 0.f, numB = 0.f, denB = 0.f;
        #pragma unroll
        for (int jp = 0; jp < 5; jp++) {
            float v0 = lo2(vp[jp]), v1 = hi2(vp[jp]);
            numA = __fmaf_rn(eA[2*jp], v0, numA);
            numA = __fmaf_rn(eA[2*jp + 1], v1, numA);
            denA += eA[2*jp] + eA[2*jp + 1];
            numB = __fmaf_rn(eB[2*jp], v0, numB);
            numB = __fmaf_rn(eB[2*jp + 1], v1, numB);
            denB += eB[2*jp] + eB[2*jp + 1];
        }
        res[2*ip]     = __fdividef(numA, denA);
        res[2*ip + 1] = __fdividef(numB, denB);
    }

    // ---- output: 5 x float2 per thread ----
    float2* op = (float2*)(out + (size_t)(blockIdx.x * TPB + t) * 10);
    #pragma unroll
    for (int p = 0; p < 5; p++) op[p] = make_float2(res[2*p], res[2*p + 1]);
}

extern "C" void kernel_launch(void* const* d_in, const int* in_sizes, int n_in,
                              void* d_out, int out_size) {
    const float* x  = (const float*)d_in[0];
    const float* Wk = (const float*)d_in[1];
    const float* bk = (const float*)d_in[2];
    const float* Wq = (const float*)d_in[3];
    const float* bq = (const float*)d_in[4];
    const float* Wv = (const float*)d_in[5];
    const float* bv = (const float*)d_in[6];
    int B = in_sizes[0] / 60;            // 524288
    int blocks = B / TPB;                // 4096
    attn_kernel<<<blocks, TPB>>>(x, Wk, bk, Wq, bq, Wv, bv, (float*)d_out);
}

// round 16
// speedup vs baseline: 1.2614x; 1.0177x over previous
#include <cuda_runtime.h>

#define TPB 128
#define XPAD 62   // per-problem smem stride (even -> 8B-aligned LDS.64; 2-way conflicts max)

typedef unsigned long long ull;

__device__ __forceinline__ ull pk(float lo, float hi) {
    ull r; asm("mov.b64 %0, {%1, %2};" : "=l"(r) : "f"(lo), "f"(hi)); return r;
}
__device__ __forceinline__ float lo2(ull v) { return __uint_as_float((unsigned)v); }
__device__ __forceinline__ float hi2(ull v) { return __uint_as_float((unsigned)(v >> 32)); }
__device__ __forceinline__ ull fma2(ull a, ull b, ull c) {
    ull d; asm("fma.rn.f32x2 %0, %1, %2, %3;" : "=l"(d) : "l"(a), "l"(b), "l"(c)); return d;
}
__device__ __forceinline__ ull mul2(ull a, ull b) {
    ull d; asm("mul.rn.f32x2 %0, %1, %2;" : "=l"(d) : "l"(a), "l"(b)); return d;
}
__device__ __forceinline__ ull add2(ull a, ull b) {
    ull d; asm("add.rn.f32x2 %0, %1, %2;" : "=l"(d) : "l"(a), "l"(b)); return d;
}
__device__ __forceinline__ float ex2(float x) {
    float r; asm("ex2.approx.f32 %0, %1;" : "=f"(r) : "f"(x)); return r;
}

// One thread = one batch problem. Transposed smem: x[j][d] at d*10+j.
// Phase 2 (R15 winning shape): per query pair, ALL 10 packed score chains first,
// then 20 ex2 batched, then -- NEW -- PACKED num/den accumulation (fma2/add2),
// cutting ~90 fma-pipe slots/thread at 94.8% pipe saturation.
// S'_ij = (x_i^T M x_j + r.x_j)*log2(e); out_i = sum 2^s vsum / sum 2^s.
// smem constants (dup-packed float2): [0..35] M*L2E, [36..41] r*L2E, [42..47] wv, [48] cv
__global__ __launch_bounds__(TPB, 3) void attn_kernel(
    const float* __restrict__ x,
    const float* __restrict__ Wk, const float* __restrict__ bk,
    const float* __restrict__ Wq, const float* __restrict__ bq,
    const float* __restrict__ Wv, const float* __restrict__ bv,
    float* __restrict__ out)
{
    __shared__ float2 cst[49];
    __shared__ float  xs[TPB * XPAD];
    const int t = threadIdx.x;

    // ---- per-block precompute of dup-packed constants ----
    if (t < 49) {
        const float L2E = 1.4426950408889634f;
        float s = 0.f;
        if (t < 36) {                    // M[a][b] = sum_e Wq[e][a] Wk[e][b]  (*L2E)
            int a = t / 6, b = t % 6;
            #pragma unroll
            for (int e = 0; e < 6; e++) s += Wq[e*6 + a] * Wk[e*6 + b];
            s *= L2E;
        } else if (t < 42) {             // r[b] = sum_e bq[e] Wk[e][b]  (*L2E)
            int b = t - 36;
            #pragma unroll
            for (int e = 0; e < 6; e++) s += bq[e] * Wk[e*6 + b];
            s *= L2E;
        } else if (t < 48) {             // wv[d] = colsum(Wv)
            int d = t - 42;
            #pragma unroll
            for (int e = 0; e < 6; e++) s += Wv[e*6 + d];
        } else {                         // cv = sum(bv)
            #pragma unroll
            for (int e = 0; e < 6; e++) s += bv[e];
        }
        cst[t] = make_float2(s, s);
    }

    // ---- staging (threads 0..119): 16 float4 each, loop-invariant transpose addressing ----
    if (t < 120) {
        const float4* xg = (const float4*)(x + (size_t)blockIdx.x * (TPB * 60)) + t;
        int tb = (4 * t) / 60;
        int te = 4 * t - 60 * tb;
        int j0 = te / 6, d0 = te - 6 * j0;
        int ro = (d0 == 4) ? 59 : 0;
        int a0 = tb * XPAD + d0 * 10 + j0;
        #pragma unroll
        for (int i = 0; i < 16; i++) {
            float4 v = xg[i * 120];
            xs[a0]           = v.x;
            xs[a0 + 10]      = v.y;
            xs[a0 + 20 - ro] = v.z;
            xs[a0 + 30 - ro] = v.w;
            a0 += 8 * XPAD;
        }
    }
    __syncthreads();

    const float* xp = &xs[t * XPAD];
    const ull*   XX = (const ull*)xp;               // XX[d*5 + m] = (x[2m][d], x[2m+1][d])
    const ull*   C  = reinterpret_cast<const ull*>(cst);

    // ---- phase 1, d-outer, fully packed ----
    ull G[6][5], hp[5], vp[5];
    {   // d = 0
        ull xx0 = XX[0], xx1 = XX[1], xx2 = XX[2], xx3 = XX[3], xx4 = XX[4];
        #pragma unroll
        for (int a = 0; a < 6; a++) {
            ull m = C[a*6];
            G[a][0] = mul2(m, xx0); G[a][1] = mul2(m, xx1); G[a][2] = mul2(m, xx2);
            G[a][3] = mul2(m, xx3); G[a][4] = mul2(m, xx4);
        }
        ull r = C[36], w = C[42], cv = C[48];
        hp[0] = mul2(r, xx0); hp[1] = mul2(r, xx1); hp[2] = mul2(r, xx2);
        hp[3] = mul2(r, xx3); hp[4] = mul2(r, xx4);
        vp[0] = fma2(w, xx0, cv); vp[1] = fma2(w, xx1, cv); vp[2] = fma2(w, xx2, cv);
        vp[3] = fma2(w, xx3, cv); vp[4] = fma2(w, xx4, cv);
    }
    #pragma unroll
    for (int d = 1; d < 6; d++) {
        ull xx[5];
        #pragma unroll
        for (int jp = 0; jp < 5; jp++) xx[jp] = XX[d*5 + jp];
        #pragma unroll
        for (int a = 0; a < 6; a++) {
            ull m = C[a*6 + d];
            #pragma unroll
            for (int jp = 0; jp < 5; jp++) G[a][jp] = fma2(m, xx[jp], G[a][jp]);
        }
        ull r = C[36 + d], w = C[42 + d];
        #pragma unroll
        for (int jp = 0; jp < 5; jp++) {
            hp[jp] = fma2(r, xx[jp], hp[jp]);
            vp[jp] = fma2(w, xx[jp], vp[jp]);
        }
    }

    // ---- phase 2: query pairs; ALL scores -> ALL ex2 -> PACKED accumulate ----
    float res[10];
    #pragma unroll
    for (int ip = 0; ip < 5; ip++) {     // queries 2ip, 2ip+1
        ull XA[6], XB[6];
        #pragma unroll
        for (int a = 0; a < 6; a++) {
            ull xq = XX[a*5 + ip];       // one LDS.64 serves both queries
            float xa = lo2(xq), xb = hi2(xq);
            XA[a] = pk(xa, xa);
            XB[a] = pk(xb, xb);
        }

        // 10 independent 6-deep fma2 chains (max ILP before any MUFU)
        ull sA[5], sB[5];
        #pragma unroll
        for (int jp = 0; jp < 5; jp++) {
            ull a0 = fma2(XA[0], G[0][jp], hp[jp]);
            ull b0 = fma2(XB[0], G[0][jp], hp[jp]);
            #pragma unroll
            for (int a = 1; a < 6; a++) {
                a0 = fma2(XA[a], G[a][jp], a0);
                b0 = fma2(XB[a], G[a][jp], b0);
            }
            sA[jp] = a0;
            sB[jp] = b0;
        }

        // 20 ex2 batched back-to-back, immediately repacked (pk = alu-pipe MOV)
        ull eA[5], eB[5];
        #pragma unroll
        for (int jp = 0; jp < 5; jp++) {
            eA[jp] = pk(ex2(lo2(sA[jp])), ex2(hi2(sA[jp])));
            eB[jp] = pk(ex2(lo2(sB[jp])), ex2(hi2(sB[jp])));
        }

        // packed num/den accumulate: 9 fma-pipe ops/query vs 20 scalar
        ull nA = mul2(eA[0], vp[0]), dA = eA[0];
        ull nB = mul2(eB[0], vp[0]), dB = eB[0];
        #pragma unroll
        for (int jp = 1; jp < 5; jp++) {
            nA = fma2(eA[jp], vp[jp], nA);  dA = add2(dA, eA[jp]);
            nB = fma2(eB[jp], vp[jp], nB);  dB = add2(dB, eB[jp]);
        }
        res[2*ip]     = __fdividef(lo2(nA) + hi2(nA), lo2(dA) + hi2(dA));
        res[2*ip + 1] = __fdividef(lo2(nB) + hi2(nB), lo2(dB) + hi2(dB));
    }

    // ---- output: 5 x float2 per thread ----
    float2* op = (float2*)(out + (size_t)(blockIdx.x * TPB + t) * 10);
    #pragma unroll
    for (int p = 0; p < 5; p++) op[p] = make_float2(res[2*p], res[2*p + 1]);
}

extern "C" void kernel_launch(void* const* d_in, const int* in_sizes, int n_in,
                              void* d_out, int out_size) {
    const float* x  = (const float*)d_in[0];
    const float* Wk = (const float*)d_in[1];
    const float* bk = (const float*)d_in[2];
    const float* Wq = (const float*)d_in[3];
    const float* bq = (const float*)d_in[4];
    const float* Wv = (const float*)d_in[5];
    const float* bv = (const float*)d_in[6];
    int B = in_sizes[0] / 60;            // 524288
    int blocks = B / TPB;                // 4096
    attn_kernel<<<blocks, TPB>>>(x, Wk, bk, Wq, bq, Wv, bv, (float*)d_out);
}